// round 15
// baseline (speedup 1.0000x reference)
#include <cuda_runtime.h>
#include <cuda_bf16.h>
#include <math.h>
#include <stdint.h>

// Problem shapes (fixed for this dataset entry)
#define B_  64
#define T_  20
#define F_  2048
#define E_  512
#define G_  1024
#define V_  32000
#define S3_ 3072            // 3*G
#define TB_ 1280            // T*B

// ---------------- scratch (device globals; no allocations allowed) ----------
__device__ float g_img_scale[E_];
__device__ float g_gi[TB_ * S3_];              // gi_all (includes b_ih)
__device__ float g_gh[4 * B_ * S3_];           // four split-K partials
__device__ float g_hall[TB_ * G_];             // h fp32 chain
__device__ unsigned g_grubar;                  // persistent-GRU barrier counter

// compact split-bf16 operands: rows = [hi (K) | lo (K)], row stride 2K
__device__ __nv_bfloat16 g_xs  [TB_ * 2 * E_];       // x'    [1280, 1024]
__device__ __nv_bfloat16 g_wihs[S3_ * 2 * E_];       // W_ih' [3072, 1024]
__device__ __nv_bfloat16 g_whhs[S3_ * 2 * G_];       // W_hh' [3072, 2048]
__device__ __nv_bfloat16 g_hs  [TB_ * 2 * G_];       // h'    [1280, 2048]
__device__ __nv_bfloat16 g_fcs [(long)V_ * 2 * G_];  // fc'   [32000, 2048]

// ============================ PTX helpers ====================================
__device__ __forceinline__ uint32_t smem_u32(const void* p) {
    uint32_t a;
    asm("{ .reg .u64 t; cvta.to.shared.u64 t, %1; cvt.u32.u64 %0, t; }" : "=r"(a) : "l"(p));
    return a;
}
__device__ __forceinline__ void cp16(uint32_t dst, const void* src) {
    asm volatile("cp.async.cg.shared.global [%0], [%1], 16;\n" :: "r"(dst), "l"(src));
}
__device__ __forceinline__ void cp_commit() { asm volatile("cp.async.commit_group;\n"); }
template<int N> __device__ __forceinline__ void cp_wait() {
    asm volatile("cp.async.wait_group %0;\n" :: "n"(N));
}
__device__ __forceinline__ void ldsm4(uint32_t* r, uint32_t addr) {
    asm volatile("ldmatrix.sync.aligned.m8n8.x4.shared.b16 {%0,%1,%2,%3}, [%4];"
                 : "=r"(r[0]), "=r"(r[1]), "=r"(r[2]), "=r"(r[3]) : "r"(addr));
}
__device__ __forceinline__ void mma16816(float* c, const uint32_t* a, const uint32_t* b) {
    asm volatile("mma.sync.aligned.m16n8k16.row.col.f32.bf16.bf16.f32 "
                 "{%0,%1,%2,%3}, {%4,%5,%6,%7}, {%8,%9}, {%0,%1,%2,%3};"
                 : "+f"(c[0]), "+f"(c[1]), "+f"(c[2]), "+f"(c[3])
                 : "r"(a[0]), "r"(a[1]), "r"(a[2]), "r"(a[3]), "r"(b[0]), "r"(b[1]));
}

// ================= rownorm (img): out[r] = g[r] * rsqrt(sum v^2) =============
__global__ void rownorm_scale(const float* __restrict__ Vmat,
                              const float* __restrict__ g,
                              float* __restrict__ out, int K) {
    int row = blockIdx.x;
    const float4* v = (const float4*)(Vmat + (long)row * K);
    float s = 0.f;
    int K4 = K >> 2;
    for (int i = threadIdx.x; i < K4; i += blockDim.x) {
        float4 q = v[i];
        s += q.x * q.x + q.y * q.y + q.z * q.z + q.w * q.w;
    }
    #pragma unroll
    for (int o = 16; o; o >>= 1) s += __shfl_xor_sync(0xffffffffu, s, o);
    __shared__ float ws[8];
    if ((threadIdx.x & 31) == 0) ws[threadIdx.x >> 5] = s;
    __syncthreads();
    if (threadIdx.x < 32) {
        s = (threadIdx.x < (blockDim.x >> 5)) ? ws[threadIdx.x] : 0.f;
        #pragma unroll
        for (int o = 4; o; o >>= 1) s += __shfl_xor_sync(0xffffffffu, s, o);
        if (threadIdx.x == 0) out[row] = g[row] * rsqrtf(s);
    }
}

// ===== fused fc prep: per row, norm-scale then write compact [hi|lo] =========
__global__ void prep_fc(const float* __restrict__ fc_v,
                        const float* __restrict__ fc_g,
                        __nv_bfloat16* __restrict__ fcs) {
    int row = blockIdx.x;                    // 32000, blockDim 128
    const float4* v = (const float4*)(fc_v + (long)row * G_);
    float4 a = v[threadIdx.x];               // elems 4*tid   .. +3
    float4 b = v[128 + threadIdx.x];         // elems 512+4*tid .. +3
    float s = a.x * a.x + a.y * a.y + a.z * a.z + a.w * a.w
            + b.x * b.x + b.y * b.y + b.z * b.z + b.w * b.w;
    #pragma unroll
    for (int o = 16; o; o >>= 1) s += __shfl_xor_sync(0xffffffffu, s, o);
    __shared__ float ws[4];
    if ((threadIdx.x & 31) == 0) ws[threadIdx.x >> 5] = s;
    __syncthreads();
    __shared__ float sc;
    if (threadIdx.x == 0) {
        float tot = ws[0] + ws[1] + ws[2] + ws[3];
        sc = fc_g[row] * rsqrtf(tot);
    }
    __syncthreads();
    float scale = sc;
    __nv_bfloat16* base = fcs + (long)row * (2 * G_);
    float va[4] = {a.x, a.y, a.z, a.w};
    float vb[4] = {b.x, b.y, b.z, b.w};
    #pragma unroll
    for (int j = 0; j < 4; j++) {
        float vs = va[j] * scale;
        __nv_bfloat16 hi = __float2bfloat16(vs);
        base[threadIdx.x * 4 + j] = hi;
        base[G_ + threadIdx.x * 4 + j] = __float2bfloat16(vs - __bfloat162float(hi));
    }
    #pragma unroll
    for (int j = 0; j < 4; j++) {
        float vs = vb[j] * scale;
        __nv_bfloat16 hi = __float2bfloat16(vs);
        base[512 + threadIdx.x * 4 + j] = hi;
        base[G_ + 512 + threadIdx.x * 4 + j] = __float2bfloat16(vs - __bfloat162float(hi));
    }
}

// === prep combo: gather embeddings (t>=1) -> xs [hi|lo] + W_ih' [hi|lo] ======
#define GATHER_BLKS ((T_ - 1) * B_)          // 1216
#define WIH_BLKS    ((S3_ * E_) / 256)       // 6144
__global__ void prep_combo(const int* __restrict__ ids,
                           const float* __restrict__ emb,
                           const float* __restrict__ W_ih,
                           __nv_bfloat16* __restrict__ xs,
                           __nv_bfloat16* __restrict__ wihs) {
    if (blockIdx.x < GATHER_BLKS) {
        int r = blockIdx.x;                  // blockDim = 128
        int t = r / B_ + 1;
        int b = r % B_;
        int tok = ids[b * T_ + t];
        float4 v = ((const float4*)(emb + (long)tok * E_))[threadIdx.x];
        __nv_bfloat16* d = xs + ((long)t * B_ + b) * (2 * E_) + threadIdx.x * 4;
        float vv[4] = {v.x, v.y, v.z, v.w};
        #pragma unroll
        for (int j = 0; j < 4; j++) {
            __nv_bfloat16 hi = __float2bfloat16(vv[j]);
            d[j] = hi;
            d[E_ + j] = __float2bfloat16(vv[j] - __bfloat162float(hi));
        }
    } else {                                 // W_ih split [hi|lo]
        long i = (long)(blockIdx.x - GATHER_BLKS) * 256 + threadIdx.x * 2;
        #pragma unroll
        for (int e = 0; e < 2; e++) {
            long ii = i + e;
            long row = ii >> 9;              // K = 512
            int k = (int)(ii & 511);
            float v = W_ih[ii];
            __nv_bfloat16 hi = __float2bfloat16(v);
            __nv_bfloat16* d = wihs + row * (2L * E_) + k;
            d[0] = hi;
            d[E_] = __float2bfloat16(v - __bfloat162float(hi));
        }
    }
}

// ================= split (compact [hi|lo]) for W_hh ==========================
__global__ void split2(const float* __restrict__ src,
                       __nv_bfloat16* __restrict__ dst, int K, int logK) {
    long i = (long)blockIdx.x * 256 + threadIdx.x;
    long row = i >> logK;
    int k = (int)(i & (K - 1));
    float v = src[i];
    __nv_bfloat16 hi = __float2bfloat16(v);
    __nv_bfloat16* d = dst + row * (2L * K) + k;
    d[0] = hi;
    d[K] = __float2bfloat16(v - __bfloat162float(hi));
}

// ====== fp32 SIMT GEMM; writes compact bf16 split rows [hi|lo] width 2N ======
template<int MT, int NT, int KT, int TM, int TN>
__global__ void __launch_bounds__((MT / TM) * (NT / TN))
gemm_img(const float* __restrict__ A, const float* __restrict__ Bt,
         const float* __restrict__ scale, const float* __restrict__ bias,
         __nv_bfloat16* __restrict__ H, int M, int N, int K) {
    constexpr int NTHR = (MT / TM) * (NT / TN);
    __shared__ float As[KT][MT];
    __shared__ float Bs[KT][NT];
    const int tid = threadIdx.x;
    const int NTT = NT / TN;
    const int tx = tid % NTT;
    const int ty = tid / NTT;
    const int m0 = blockIdx.y * MT;
    const int n0 = blockIdx.x * NT;
    float acc[TM][TN];
    #pragma unroll
    for (int i = 0; i < TM; i++)
        #pragma unroll
        for (int j = 0; j < TN; j++) acc[i][j] = 0.f;
    const int KT4 = KT / 4;
    for (int k0 = 0; k0 < K; k0 += KT) {
        for (int p = tid; p < MT * KT4; p += NTHR) {
            int r = p / KT4, cq = p % KT4;
            float4 v = *(const float4*)(A + (long)(m0 + r) * K + k0 + cq * 4);
            As[cq * 4 + 0][r] = v.x; As[cq * 4 + 1][r] = v.y;
            As[cq * 4 + 2][r] = v.z; As[cq * 4 + 3][r] = v.w;
        }
        for (int p = tid; p < NT * KT4; p += NTHR) {
            int r = p / KT4, cq = p % KT4;
            float4 v = *(const float4*)(Bt + (long)(n0 + r) * K + k0 + cq * 4);
            Bs[cq * 4 + 0][r] = v.x; Bs[cq * 4 + 1][r] = v.y;
            Bs[cq * 4 + 2][r] = v.z; Bs[cq * 4 + 3][r] = v.w;
        }
        __syncthreads();
        #pragma unroll
        for (int kk = 0; kk < KT; kk++) {
            float a[TM], b[TN];
            #pragma unroll
            for (int i = 0; i < TM; i++) a[i] = As[kk][ty * TM + i];
            #pragma unroll
            for (int j = 0; j < TN; j++) b[j] = Bs[kk][tx * TN + j];
            #pragma unroll
            for (int i = 0; i < TM; i++)
                #pragma unroll
                for (int j = 0; j < TN; j++)
                    acc[i][j] = fmaf(a[i], b[j], acc[i][j]);
        }
        __syncthreads();
    }
    #pragma unroll
    for (int i = 0; i < TM; i++) {
        int m = m0 + ty * TM + i;
        #pragma unroll
        for (int j = 0; j < TN; j++) {
            int n = n0 + tx * TN + j;
            float v = acc[i][j] * scale[n] + bias[n];
            __nv_bfloat16 hi = __float2bfloat16(v);
            __nv_bfloat16* d = H + (long)m * (2 * N) + n;
            d[0] = hi;
            d[N] = __float2bfloat16(v - __bfloat162float(hi));
        }
    }
}

// ===== mma bf16 GEMM (champion cfg) with compact-operand chunk remap =========
// Logical K' = 3*NK*64 (3 terms); physical rows = [hi|lo], stride 2*NK*64.
// chunk t: A ca = t<2NK ? t : t-2NK ; B cb = t<2NK ? t&(NK-1) : t-NK
// EPI 0: C[m*N+n]   EPI 1: caption permute t=m>>6, b=m&63 -> C[b][t][n]
#define STAGE_B  32768          // A 128x64 (16KB) + B 128x64 (16KB)
#define NSTAGE   3
#define MMA_SMEM (NSTAGE * STAGE_B)

template<int EPI, int NK>
__global__ void __launch_bounds__(512, 2)
gemm_mma(const __nv_bfloat16* __restrict__ A, const __nv_bfloat16* __restrict__ Bt,
         const float* __restrict__ bias, float* __restrict__ C, int M, int N) {
    extern __shared__ char smem[];
    const uint32_t sb = smem_u32(smem);
    const int tid = threadIdx.x;
    const int wid = tid >> 5;
    const int lane = tid & 31;
    const int m0 = blockIdx.x * 128;
    const int n0 = blockIdx.y * 128;
    const int wm = wid >> 2;        // 0..3  (32 rows each)
    const int wn = wid & 3;         // 0..3  (32 cols each)
    const int KA = 2 * NK * 64;     // physical row stride

    float acc[2][4][4];
    #pragma unroll
    for (int i = 0; i < 2; i++)
        #pragma unroll
        for (int j = 0; j < 4; j++)
            #pragma unroll
            for (int q = 0; q < 4; q++) acc[i][j][q] = 0.f;

    auto load_stage = [&](int t, int s) {
        const int ca = (t < 2 * NK) ? t : t - 2 * NK;
        const int cb = (t < 2 * NK) ? (t & (NK - 1)) : t - NK;
        const uint32_t base = sb + (uint32_t)s * STAGE_B;
        const __nv_bfloat16* Ap = A + (long)m0 * KA + (long)ca * 64;
        const __nv_bfloat16* Bp = Bt + (long)n0 * KA + (long)cb * 64;
        #pragma unroll
        for (int i = 0; i < 2; i++) {
            int q = tid + i * 512;                 // 0..1023
            int r = q >> 3, c = q & 7;
            cp16(base + r * 128 + ((c ^ (r & 7)) << 4), Ap + (long)r * KA + c * 8);
        }
        #pragma unroll
        for (int i = 0; i < 2; i++) {
            int q = tid + i * 512;
            int r = q >> 3, c = q & 7;
            cp16(base + 16384 + r * 128 + ((c ^ (r & 7)) << 4), Bp + (long)r * KA + c * 8);
        }
        cp_commit();
    };

    const int NT = 3 * NK;
    load_stage(0, 0);
    load_stage(1, 1);

    for (int t = 0; t < NT; t++) {
        if (t == NT - 1) cp_wait<0>(); else cp_wait<1>();
        __syncthreads();
        if (t + 2 < NT) load_stage(t + 2, (t + 2) % NSTAGE);

        const uint32_t ab = sb + (uint32_t)(t % NSTAGE) * STAGE_B;
        const uint32_t bb = ab + 16384;
        #pragma unroll
        for (int ks = 0; ks < 4; ks++) {
            uint32_t afr[2][4], bfr[2][4];
            #pragma unroll
            for (int mi = 0; mi < 2; mi++) {
                int R = wm * 32 + mi * 16 + (lane & 7) + (((lane >> 3) & 1) << 3);
                int cc = ks * 2 + (lane >> 4);
                ldsm4(afr[mi], ab + R * 128 + (((cc ^ (R & 7)) & 7) << 4));
            }
            #pragma unroll
            for (int bp = 0; bp < 2; bp++) {
                int R = wn * 32 + bp * 16 + (lane & 7) + ((lane >> 4) << 3);
                int cc = ks * 2 + ((lane >> 3) & 1);
                ldsm4(bfr[bp], bb + R * 128 + (((cc ^ (R & 7)) & 7) << 4));
            }
            #pragma unroll
            for (int mi = 0; mi < 2; mi++)
                #pragma unroll
                for (int nj = 0; nj < 4; nj++)
                    mma16816(acc[mi][nj], afr[mi], &bfr[nj >> 1][(nj & 1) * 2]);
        }
    }

    const int g = lane >> 2;
    const int tg = lane & 3;
    #pragma unroll
    for (int mi = 0; mi < 2; mi++) {
        #pragma unroll
        for (int half = 0; half < 2; half++) {
            int m = m0 + wm * 32 + mi * 16 + g + half * 8;
            float* dst;
            if (EPI == 0) {
                dst = C + (long)m * N;
            } else {
                int tt = m >> 6, b = m & 63;
                dst = C + (long)b * ((long)T_ * V_) + (long)tt * V_;
            }
            #pragma unroll
            for (int nj = 0; nj < 4; nj++) {
                int n = n0 + wn * 32 + nj * 8 + tg * 2;
                float2 v;
                v.x = acc[mi][nj][half * 2 + 0] + __ldg(bias + n + 0);
                v.y = acc[mi][nj][half * 2 + 1] + __ldg(bias + n + 1);
                *(float2*)(dst + n) = v;
            }
        }
    }
}

// ===== persistent GRU: all 20 steps, 192 CTAs, device-wide barrier ===========
#define GRU_CTAS  192           // 48 n-tiles x 4 k-splits; all co-resident
#define GSTAGE_B  16384         // A 64x64 (8KB) + B 64x64 (8KB)
#define GRU_SMEM  (NSTAGE * GSTAGE_B)

__device__ __forceinline__ void gbar(unsigned target) {
    __syncthreads();
    __threadfence();
    if (threadIdx.x == 0) {
        atomicAdd(&g_grubar, 1u);
        while (*(volatile unsigned*)&g_grubar < target) { }
    }
    __syncthreads();
}

__global__ void __launch_bounds__(128, 2)
gru_persist(const __nv_bfloat16* __restrict__ whhs,   // [3072, 2048] compact
            const float* __restrict__ gi,
            const float* __restrict__ b_hh,
            float* __restrict__ gh,                    // [4][B,3G]
            float* __restrict__ hall,                  // [T][B,G]
            __nv_bfloat16* __restrict__ hs) {          // [T*B, 2048] compact
    extern __shared__ char smem[];
    const uint32_t sb = smem_u32(smem);
    const int tid = threadIdx.x;
    const int wid = tid >> 5;
    const int lane = tid & 31;
    const int nb = blockIdx.x % 48;
    const int ky = blockIdx.x / 48;          // 0..3
    const int n0 = nb * 64;
    const int wm = wid >> 1, wn = wid & 1;
    const int KA = 2048;                     // physical row stride (NK=16)
    unsigned seq = 0;

    for (int t = 0; t < T_; t++) {
        if (t > 0) {
            const __nv_bfloat16* A = hs + (long)(t - 1) * B_ * KA;
            float acc[2][4][4];
            #pragma unroll
            for (int i = 0; i < 2; i++)
                #pragma unroll
                for (int j = 0; j < 4; j++)
                    #pragma unroll
                    for (int q = 0; q < 4; q++) acc[i][j][q] = 0.f;

            auto load_stage = [&](int lt, int s) {
                const int ts = ky * 12 + lt;             // global chunk 0..47
                const int ca = (ts < 32) ? ts : ts - 32;
                const int cb = (ts < 32) ? (ts & 15) : ts - 16;
                const uint32_t base = sb + (uint32_t)s * GSTAGE_B;
                const __nv_bfloat16* Ap = A + (long)ca * 64;
                const __nv_bfloat16* Bp = whhs + (long)n0 * KA + (long)cb * 64;
                #pragma unroll
                for (int i = 0; i < 4; i++) {
                    int q = tid + i * 128;               // 0..511
                    int r = q >> 3, c = q & 7;
                    cp16(base + r * 128 + ((c ^ (r & 7)) << 4), Ap + (long)r * KA + c * 8);
                }
                #pragma unroll
                for (int i = 0; i < 4; i++) {
                    int q = tid + i * 128;
                    int r = q >> 3, c = q & 7;
                    cp16(base + 8192 + r * 128 + ((c ^ (r & 7)) << 4), Bp + (long)r * KA + c * 8);
                }
                cp_commit();
            };

            load_stage(0, 0);
            load_stage(1, 1);
            for (int lt = 0; lt < 12; lt++) {
                if (lt == 11) cp_wait<0>(); else cp_wait<1>();
                __syncthreads();
                if (lt + 2 < 12) load_stage(lt + 2, (lt + 2) % NSTAGE);

                const uint32_t ab = sb + (uint32_t)(lt % NSTAGE) * GSTAGE_B;
                const uint32_t bb = ab + 8192;
                #pragma unroll
                for (int ks = 0; ks < 4; ks++) {
                    uint32_t afr[2][4], bfr[2][4];
                    #pragma unroll
                    for (int mi = 0; mi < 2; mi++) {
                        int R = wm * 32 + mi * 16 + (lane & 7) + (((lane >> 3) & 1) << 3);
                        int cc = ks * 2 + (lane >> 4);
                        ldsm4(afr[mi], ab + R * 128 + (((cc ^ (R & 7)) & 7) << 4));
                    }
                    #pragma unroll
                    for (int bp = 0; bp < 2; bp++) {
                        int R = wn * 32 + bp * 16 + (lane & 7) + ((lane >> 4) << 3);
                        int cc = ks * 2 + ((lane >> 3) & 1);
                        ldsm4(bfr[bp], bb + R * 128 + (((cc ^ (R & 7)) & 7) << 4));
                    }
                    #pragma unroll
                    for (int mi = 0; mi < 2; mi++)
                        #pragma unroll
                        for (int nj = 0; nj < 4; nj++)
                            mma16816(acc[mi][nj], afr[mi], &bfr[nj >> 1][(nj & 1) * 2]);
                }
            }
            // write partial to gh[ky]
            float* Cy = gh + (long)ky * B_ * S3_;
            const int gq = lane >> 2;
            const int tg = lane & 3;
            #pragma unroll
            for (int mi = 0; mi < 2; mi++) {
                #pragma unroll
                for (int half = 0; half < 2; half++) {
                    int m = wm * 32 + mi * 16 + gq + half * 8;
                    #pragma unroll
                    for (int nj = 0; nj < 4; nj++) {
                        int n = n0 + wn * 32 + nj * 8 + tg * 2;
                        float2 v;
                        v.x = acc[mi][nj][half * 2 + 0];
                        v.y = acc[mi][nj][half * 2 + 1];
                        *(float2*)(Cy + (long)m * S3_ + n) = v;
                    }
                }
            }
        }
        gbar(++seq * GRU_CTAS);          // gh ready (or trivially at t=0)

        // gate phase: cover B*G = 65536 elems with 24576 threads
        const float* git = gi + (long)t * B_ * S3_;
        for (int i = blockIdx.x * 128 + tid; i < B_ * G_; i += GRU_CTAS * 128) {
            int b = i >> 10;
            int g = i & (G_ - 1);
            long o = (long)b * S3_;
            float ir = git[o + g];
            float iz = git[o + G_ + g];
            float in_ = git[o + 2 * G_ + g];
            float hr, hz, hn;
            if (t == 0) {
                hr = b_hh[g]; hz = b_hh[G_ + g]; hn = b_hh[2 * G_ + g];
            } else {
                const long P = (long)B_ * S3_;
                hr = __ldcg(gh + o + g) + __ldcg(gh + P + o + g)
                   + __ldcg(gh + 2 * P + o + g) + __ldcg(gh + 3 * P + o + g) + b_hh[g];
                hz = __ldcg(gh + o + G_ + g) + __ldcg(gh + P + o + G_ + g)
                   + __ldcg(gh + 2 * P + o + G_ + g) + __ldcg(gh + 3 * P + o + G_ + g)
                   + b_hh[G_ + g];
                hn = __ldcg(gh + o + 2 * G_ + g) + __ldcg(gh + P + o + 2 * G_ + g)
                   + __ldcg(gh + 2 * P + o + 2 * G_ + g) + __ldcg(gh + 3 * P + o + 2 * G_ + g)
                   + b_hh[2 * G_ + g];
            }
            float r = 1.f / (1.f + expf(-(ir + hr)));
            float z = 1.f / (1.f + expf(-(iz + hz)));
            float n = tanhf(in_ + r * hn);
            float hp = (t == 0) ? 0.f : hall[(long)(t - 1) * B_ * G_ + i];
            float hv = (1.f - z) * n + z * hp;
            hall[(long)t * B_ * G_ + i] = hv;
            __nv_bfloat16 hi = __float2bfloat16(hv);
            __nv_bfloat16* d = hs + ((long)t * B_ + b) * KA + g;
            d[0] = hi;
            d[G_] = __float2bfloat16(hv - __bfloat162float(hi));
        }
        gbar(++seq * GRU_CTAS);          // hs(t) ready for gemm(t+1)
    }
}

// ================= launch ====================================================
extern "C" void kernel_launch(void* const* d_in, const int* in_sizes, int n_in,
                              void* d_out, int out_size) {
    (void)in_sizes; (void)n_in; (void)out_size;
    const float* features  = (const float*)d_in[0];
    const int*   input_ids = (const int*)  d_in[1];
    const float* emb_table = (const float*)d_in[2];
    const float* img_v     = (const float*)d_in[3];
    const float* img_g     = (const float*)d_in[4];
    const float* img_b     = (const float*)d_in[5];
    const float* W_ih      = (const float*)d_in[6];
    const float* W_hh      = (const float*)d_in[7];
    const float* b_ih      = (const float*)d_in[8];
    const float* b_hh      = (const float*)d_in[9];
    const float* fc_v      = (const float*)d_in[10];
    const float* fc_g      = (const float*)d_in[11];
    const float* fc_b      = (const float*)d_in[12];
    float* out = (float*)d_out;

    float *gi, *gh, *hall, *img_s;
    __nv_bfloat16 *xs, *wihs, *whhs, *hs, *fcs;
    unsigned* bar;
    cudaGetSymbolAddress((void**)&gi,    g_gi);
    cudaGetSymbolAddress((void**)&gh,    g_gh);
    cudaGetSymbolAddress((void**)&hall,  g_hall);
    cudaGetSymbolAddress((void**)&img_s, g_img_scale);
    cudaGetSymbolAddress((void**)&xs,    g_xs);
    cudaGetSymbolAddress((void**)&wihs,  g_wihs);
    cudaGetSymbolAddress((void**)&whhs,  g_whhs);
    cudaGetSymbolAddress((void**)&hs,    g_hs);
    cudaGetSymbolAddress((void**)&fcs,   g_fcs);
    cudaGetSymbolAddress((void**)&bar,   g_grubar);

    cudaFuncSetAttribute((const void*)gemm_mma<0, 8>,
                         cudaFuncAttributeMaxDynamicSharedMemorySize, MMA_SMEM);
    cudaFuncSetAttribute((const void*)gemm_mma<1, 16>,
                         cudaFuncAttributeMaxDynamicSharedMemorySize, MMA_SMEM);
    cudaFuncSetAttribute((const void*)gru_persist,
                         cudaFuncAttributeMaxDynamicSharedMemorySize, GRU_SMEM);

    // 1) img weight-norm scale
    rownorm_scale<<<E_, 256>>>(img_v, img_g, img_s, F_);
    // 2) imgs_embed -> compact split rows t=0 of xs
    gemm_img<32, 32, 32, 2, 2><<<dim3(E_ / 32, B_ / 32), 256>>>(
        features, img_v, img_s, img_b, xs, B_, E_, F_);
    // 3) gather embeddings (t>=1) -> xs  +  W_ih' -> wihs
    prep_combo<<<GATHER_BLKS + WIH_BLKS, 128>>>(input_ids, emb_table, W_ih, xs, wihs);
    // 4) gi_all = x' @ W_ih'^T + b_ih   (PROFILED LAUNCH #4)
    gemm_mma<0, 8><<<dim3(TB_ / 128, S3_ / 128), 512, MMA_SMEM>>>(
        xs, wihs, b_ih, gi, TB_, S3_);

    // W_hh' and fused fc prep (independent of GRU chain start)
    split2<<<(S3_ * G_) / 256, 256>>>(W_hh, whhs, G_, 10);
    prep_fc<<<V_, 128>>>(fc_v, fc_g, fcs);

    // GRU recurrence: one persistent kernel (barrier counter zeroed per replay)
    cudaMemsetAsync(bar, 0, sizeof(unsigned));
    gru_persist<<<GRU_CTAS, 128, GRU_SMEM>>>(whhs, gi, b_hh, gh, hall, hs);

    // fc on tensor cores, permuted epilogue
    gemm_mma<1, 16><<<dim3(TB_ / 128, V_ / 128), 512, MMA_SMEM>>>(
        hs, fcs, fc_b, out, TB_, V_);
}

// round 16
// speedup vs baseline: 1.0497x; 1.0497x over previous
#include <cuda_runtime.h>
#include <cuda_bf16.h>
#include <math.h>
#include <stdint.h>

// Problem shapes (fixed for this dataset entry)
#define B_  64
#define T_  20
#define F_  2048
#define E_  512
#define G_  1024
#define V_  32000
#define S3_ 3072            // 3*G
#define TB_ 1280            // T*B

// padded compact row strides (elems): 2K + 32 -> non-power-of-2 byte stride
#define KAX 1056            // xs / wihs  (K=512)
#define KAH 2080            // hs / whhs / fcs (K=1024)

// ---------------- scratch (device globals; no allocations allowed) ----------
__device__ float g_img_scale[E_];
__device__ float g_gi[TB_ * S3_];              // gi_all (includes b_ih)
__device__ float g_gh[4 * B_ * S3_];           // four split-K partials
__device__ float g_hall[TB_ * G_];             // h fp32 chain
__device__ unsigned g_grubar;                  // persistent-GRU barrier counter

// compact split-bf16 operands: rows = [hi (K) | lo (K) | pad32]
__device__ __nv_bfloat16 g_xs  [TB_ * KAX];          // x'    [1280, 1056]
__device__ __nv_bfloat16 g_wihs[S3_ * KAX];          // W_ih' [3072, 1056]
__device__ __nv_bfloat16 g_whhs[S3_ * KAH];          // W_hh' [3072, 2080]
__device__ __nv_bfloat16 g_hs  [TB_ * KAH];          // h'    [1280, 2080]
__device__ __nv_bfloat16 g_fcs [(long)V_ * KAH];     // fc'   [32000, 2080]

// ============================ PTX helpers ====================================
__device__ __forceinline__ uint32_t smem_u32(const void* p) {
    uint32_t a;
    asm("{ .reg .u64 t; cvta.to.shared.u64 t, %1; cvt.u32.u64 %0, t; }" : "=r"(a) : "l"(p));
    return a;
}
__device__ __forceinline__ void cp16(uint32_t dst, const void* src) {
    asm volatile("cp.async.cg.shared.global [%0], [%1], 16;\n" :: "r"(dst), "l"(src));
}
__device__ __forceinline__ void cp_commit() { asm volatile("cp.async.commit_group;\n"); }
template<int N> __device__ __forceinline__ void cp_wait() {
    asm volatile("cp.async.wait_group %0;\n" :: "n"(N));
}
__device__ __forceinline__ void ldsm4(uint32_t* r, uint32_t addr) {
    asm volatile("ldmatrix.sync.aligned.m8n8.x4.shared.b16 {%0,%1,%2,%3}, [%4];"
                 : "=r"(r[0]), "=r"(r[1]), "=r"(r[2]), "=r"(r[3]) : "r"(addr));
}
__device__ __forceinline__ void mma16816(float* c, const uint32_t* a, const uint32_t* b) {
    asm volatile("mma.sync.aligned.m16n8k16.row.col.f32.bf16.bf16.f32 "
                 "{%0,%1,%2,%3}, {%4,%5,%6,%7}, {%8,%9}, {%0,%1,%2,%3};"
                 : "+f"(c[0]), "+f"(c[1]), "+f"(c[2]), "+f"(c[3])
                 : "r"(a[0]), "r"(a[1]), "r"(a[2]), "r"(a[3]), "r"(b[0]), "r"(b[1]));
}

// ================= rownorm (img): out[r] = g[r] * rsqrt(sum v^2) =============
__global__ void rownorm_scale(const float* __restrict__ Vmat,
                              const float* __restrict__ g,
                              float* __restrict__ out, int K) {
    int row = blockIdx.x;
    const float4* v = (const float4*)(Vmat + (long)row * K);
    float s = 0.f;
    int K4 = K >> 2;
    for (int i = threadIdx.x; i < K4; i += blockDim.x) {
        float4 q = v[i];
        s += q.x * q.x + q.y * q.y + q.z * q.z + q.w * q.w;
    }
    #pragma unroll
    for (int o = 16; o; o >>= 1) s += __shfl_xor_sync(0xffffffffu, s, o);
    __shared__ float ws[8];
    if ((threadIdx.x & 31) == 0) ws[threadIdx.x >> 5] = s;
    __syncthreads();
    if (threadIdx.x < 32) {
        s = (threadIdx.x < (blockDim.x >> 5)) ? ws[threadIdx.x] : 0.f;
        #pragma unroll
        for (int o = 4; o; o >>= 1) s += __shfl_xor_sync(0xffffffffu, s, o);
        if (threadIdx.x == 0) out[row] = g[row] * rsqrtf(s);
    }
}

// ===== fused fc prep: per row, norm-scale then write compact [hi|lo] =========
__global__ void prep_fc(const float* __restrict__ fc_v,
                        const float* __restrict__ fc_g,
                        __nv_bfloat16* __restrict__ fcs) {
    int row = blockIdx.x;                    // 32000, blockDim 128
    const float4* v = (const float4*)(fc_v + (long)row * G_);
    float4 a = v[threadIdx.x];               // elems 4*tid   .. +3
    float4 b = v[128 + threadIdx.x];         // elems 512+4*tid .. +3
    float s = a.x * a.x + a.y * a.y + a.z * a.z + a.w * a.w
            + b.x * b.x + b.y * b.y + b.z * b.z + b.w * b.w;
    #pragma unroll
    for (int o = 16; o; o >>= 1) s += __shfl_xor_sync(0xffffffffu, s, o);
    __shared__ float ws[4];
    if ((threadIdx.x & 31) == 0) ws[threadIdx.x >> 5] = s;
    __syncthreads();
    __shared__ float sc;
    if (threadIdx.x == 0) {
        float tot = ws[0] + ws[1] + ws[2] + ws[3];
        sc = fc_g[row] * rsqrtf(tot);
    }
    __syncthreads();
    float scale = sc;
    __nv_bfloat16* base = fcs + (long)row * KAH;
    float va[4] = {a.x, a.y, a.z, a.w};
    float vb[4] = {b.x, b.y, b.z, b.w};
    #pragma unroll
    for (int j = 0; j < 4; j++) {
        float vs = va[j] * scale;
        __nv_bfloat16 hi = __float2bfloat16(vs);
        base[threadIdx.x * 4 + j] = hi;
        base[G_ + threadIdx.x * 4 + j] = __float2bfloat16(vs - __bfloat162float(hi));
    }
    #pragma unroll
    for (int j = 0; j < 4; j++) {
        float vs = vb[j] * scale;
        __nv_bfloat16 hi = __float2bfloat16(vs);
        base[512 + threadIdx.x * 4 + j] = hi;
        base[G_ + 512 + threadIdx.x * 4 + j] = __float2bfloat16(vs - __bfloat162float(hi));
    }
}

// === prep combo: gather embeddings (t>=1) -> xs [hi|lo] + W_ih' [hi|lo] ======
#define GATHER_BLKS ((T_ - 1) * B_)          // 1216
#define WIH_BLKS    ((S3_ * E_) / 256)       // 6144
__global__ void prep_combo(const int* __restrict__ ids,
                           const float* __restrict__ emb,
                           const float* __restrict__ W_ih,
                           __nv_bfloat16* __restrict__ xs,
                           __nv_bfloat16* __restrict__ wihs) {
    if (blockIdx.x < GATHER_BLKS) {
        int r = blockIdx.x;                  // blockDim = 128
        int t = r / B_ + 1;
        int b = r % B_;
        int tok = ids[b * T_ + t];
        float4 v = ((const float4*)(emb + (long)tok * E_))[threadIdx.x];
        __nv_bfloat16* d = xs + ((long)t * B_ + b) * KAX + threadIdx.x * 4;
        float vv[4] = {v.x, v.y, v.z, v.w};
        #pragma unroll
        for (int j = 0; j < 4; j++) {
            __nv_bfloat16 hi = __float2bfloat16(vv[j]);
            d[j] = hi;
            d[E_ + j] = __float2bfloat16(vv[j] - __bfloat162float(hi));
        }
    } else {                                 // W_ih split [hi|lo]
        long i = (long)(blockIdx.x - GATHER_BLKS) * 256 + threadIdx.x * 2;
        #pragma unroll
        for (int e = 0; e < 2; e++) {
            long ii = i + e;
            long row = ii >> 9;              // K = 512
            int k = (int)(ii & 511);
            float v = W_ih[ii];
            __nv_bfloat16 hi = __float2bfloat16(v);
            __nv_bfloat16* d = wihs + row * (long)KAX + k;
            d[0] = hi;
            d[E_] = __float2bfloat16(v - __bfloat162float(hi));
        }
    }
}

// ================= split (compact [hi|lo], padded stride) for W_hh ===========
__global__ void split2(const float* __restrict__ src,
                       __nv_bfloat16* __restrict__ dst, int K, int logK, int KA) {
    long i = (long)blockIdx.x * 256 + threadIdx.x;
    long row = i >> logK;
    int k = (int)(i & (K - 1));
    float v = src[i];
    __nv_bfloat16 hi = __float2bfloat16(v);
    __nv_bfloat16* d = dst + row * (long)KA + k;
    d[0] = hi;
    d[K] = __float2bfloat16(v - __bfloat162float(hi));
}

// ====== fp32 SIMT GEMM; writes compact bf16 split rows [hi|lo] stride KAX ====
template<int MT, int NT, int KT, int TM, int TN>
__global__ void __launch_bounds__((MT / TM) * (NT / TN))
gemm_img(const float* __restrict__ A, const float* __restrict__ Bt,
         const float* __restrict__ scale, const float* __restrict__ bias,
         __nv_bfloat16* __restrict__ H, int M, int N, int K) {
    constexpr int NTHR = (MT / TM) * (NT / TN);
    __shared__ float As[KT][MT];
    __shared__ float Bs[KT][NT];
    const int tid = threadIdx.x;
    const int NTT = NT / TN;
    const int tx = tid % NTT;
    const int ty = tid / NTT;
    const int m0 = blockIdx.y * MT;
    const int n0 = blockIdx.x * NT;
    float acc[TM][TN];
    #pragma unroll
    for (int i = 0; i < TM; i++)
        #pragma unroll
        for (int j = 0; j < TN; j++) acc[i][j] = 0.f;
    const int KT4 = KT / 4;
    for (int k0 = 0; k0 < K; k0 += KT) {
        for (int p = tid; p < MT * KT4; p += NTHR) {
            int r = p / KT4, cq = p % KT4;
            float4 v = *(const float4*)(A + (long)(m0 + r) * K + k0 + cq * 4);
            As[cq * 4 + 0][r] = v.x; As[cq * 4 + 1][r] = v.y;
            As[cq * 4 + 2][r] = v.z; As[cq * 4 + 3][r] = v.w;
        }
        for (int p = tid; p < NT * KT4; p += NTHR) {
            int r = p / KT4, cq = p % KT4;
            float4 v = *(const float4*)(Bt + (long)(n0 + r) * K + k0 + cq * 4);
            Bs[cq * 4 + 0][r] = v.x; Bs[cq * 4 + 1][r] = v.y;
            Bs[cq * 4 + 2][r] = v.z; Bs[cq * 4 + 3][r] = v.w;
        }
        __syncthreads();
        #pragma unroll
        for (int kk = 0; kk < KT; kk++) {
            float a[TM], b[TN];
            #pragma unroll
            for (int i = 0; i < TM; i++) a[i] = As[kk][ty * TM + i];
            #pragma unroll
            for (int j = 0; j < TN; j++) b[j] = Bs[kk][tx * TN + j];
            #pragma unroll
            for (int i = 0; i < TM; i++)
                #pragma unroll
                for (int j = 0; j < TN; j++)
                    acc[i][j] = fmaf(a[i], b[j], acc[i][j]);
        }
        __syncthreads();
    }
    #pragma unroll
    for (int i = 0; i < TM; i++) {
        int m = m0 + ty * TM + i;
        #pragma unroll
        for (int j = 0; j < TN; j++) {
            int n = n0 + tx * TN + j;
            float v = acc[i][j] * scale[n] + bias[n];
            __nv_bfloat16 hi = __float2bfloat16(v);
            __nv_bfloat16* d = H + (long)m * KAX + n;
            d[0] = hi;
            d[N] = __float2bfloat16(v - __bfloat162float(hi));
        }
    }
}

// ===== mma bf16 GEMM (champion cfg) with compact-operand chunk remap =========
// Logical K' = 3*NK*64 (3 terms); physical rows [hi|lo|pad], stride KA elems.
// chunk t: A ca = t<2NK ? t : t-2NK ; B cb = t<2NK ? t&(NK-1) : t-NK
// EPI 0: C[m*N+n]   EPI 1: caption permute t=m>>6, b=m&63 -> C[b][t][n]
#define STAGE_B  32768          // A 128x64 (16KB) + B 128x64 (16KB)
#define NSTAGE   3
#define MMA_SMEM (NSTAGE * STAGE_B)

template<int EPI, int NK, int KA>
__global__ void __launch_bounds__(512, 2)
gemm_mma(const __nv_bfloat16* __restrict__ A, const __nv_bfloat16* __restrict__ Bt,
         const float* __restrict__ bias, float* __restrict__ C, int M, int N) {
    extern __shared__ char smem[];
    const uint32_t sb = smem_u32(smem);
    const int tid = threadIdx.x;
    const int wid = tid >> 5;
    const int lane = tid & 31;
    const int m0 = blockIdx.x * 128;
    const int n0 = blockIdx.y * 128;
    const int wm = wid >> 2;        // 0..3  (32 rows each)
    const int wn = wid & 3;         // 0..3  (32 cols each)

    float acc[2][4][4];
    #pragma unroll
    for (int i = 0; i < 2; i++)
        #pragma unroll
        for (int j = 0; j < 4; j++)
            #pragma unroll
            for (int q = 0; q < 4; q++) acc[i][j][q] = 0.f;

    auto load_stage = [&](int t, int s) {
        const int ca = (t < 2 * NK) ? t : t - 2 * NK;
        const int cb = (t < 2 * NK) ? (t & (NK - 1)) : t - NK;
        const uint32_t base = sb + (uint32_t)s * STAGE_B;
        const __nv_bfloat16* Ap = A + (long)m0 * KA + (long)ca * 64;
        const __nv_bfloat16* Bp = Bt + (long)n0 * KA + (long)cb * 64;
        #pragma unroll
        for (int i = 0; i < 2; i++) {
            int q = tid + i * 512;                 // 0..1023
            int r = q >> 3, c = q & 7;
            cp16(base + r * 128 + ((c ^ (r & 7)) << 4), Ap + (long)r * KA + c * 8);
        }
        #pragma unroll
        for (int i = 0; i < 2; i++) {
            int q = tid + i * 512;
            int r = q >> 3, c = q & 7;
            cp16(base + 16384 + r * 128 + ((c ^ (r & 7)) << 4), Bp + (long)r * KA + c * 8);
        }
        cp_commit();
    };

    const int NT = 3 * NK;
    load_stage(0, 0);
    load_stage(1, 1);

    for (int t = 0; t < NT; t++) {
        if (t == NT - 1) cp_wait<0>(); else cp_wait<1>();
        __syncthreads();
        if (t + 2 < NT) load_stage(t + 2, (t + 2) % NSTAGE);

        const uint32_t ab = sb + (uint32_t)(t % NSTAGE) * STAGE_B;
        const uint32_t bb = ab + 16384;
        #pragma unroll
        for (int ks = 0; ks < 4; ks++) {
            uint32_t afr[2][4], bfr[2][4];
            #pragma unroll
            for (int mi = 0; mi < 2; mi++) {
                int R = wm * 32 + mi * 16 + (lane & 7) + (((lane >> 3) & 1) << 3);
                int cc = ks * 2 + (lane >> 4);
                ldsm4(afr[mi], ab + R * 128 + (((cc ^ (R & 7)) & 7) << 4));
            }
            #pragma unroll
            for (int bp = 0; bp < 2; bp++) {
                int R = wn * 32 + bp * 16 + (lane & 7) + ((lane >> 4) << 3);
                int cc = ks * 2 + ((lane >> 3) & 1);
                ldsm4(bfr[bp], bb + R * 128 + (((cc ^ (R & 7)) & 7) << 4));
            }
            #pragma unroll
            for (int mi = 0; mi < 2; mi++)
                #pragma unroll
                for (int nj = 0; nj < 4; nj++)
                    mma16816(acc[mi][nj], afr[mi], &bfr[nj >> 1][(nj & 1) * 2]);
        }
    }

    const int g = lane >> 2;
    const int tg = lane & 3;
    #pragma unroll
    for (int mi = 0; mi < 2; mi++) {
        #pragma unroll
        for (int half = 0; half < 2; half++) {
            int m = m0 + wm * 32 + mi * 16 + g + half * 8;
            float* dst;
            if (EPI == 0) {
                dst = C + (long)m * N;
            } else {
                int tt = m >> 6, b = m & 63;
                dst = C + (long)b * ((long)T_ * V_) + (long)tt * V_;
            }
            #pragma unroll
            for (int nj = 0; nj < 4; nj++) {
                int n = n0 + wn * 32 + nj * 8 + tg * 2;
                float2 v;
                v.x = acc[mi][nj][half * 2 + 0] + __ldg(bias + n + 0);
                v.y = acc[mi][nj][half * 2 + 1] + __ldg(bias + n + 1);
                *(float2*)(dst + n) = v;
            }
        }
    }
}

// ===== persistent GRU: all 20 steps, 192 CTAs, device-wide barrier ===========
#define GRU_CTAS  192           // 48 n-tiles x 4 k-splits; all co-resident
#define GSTAGE_B  16384         // A 64x64 (8KB) + B 64x64 (8KB)
#define GRU_SMEM  (NSTAGE * GSTAGE_B)

__device__ __forceinline__ void gbar(unsigned target) {
    __syncthreads();
    __threadfence();
    if (threadIdx.x == 0) {
        atomicAdd(&g_grubar, 1u);
        while (*(volatile unsigned*)&g_grubar < target) { }
    }
    __syncthreads();
}

__global__ void __launch_bounds__(128, 2)
gru_persist(const __nv_bfloat16* __restrict__ whhs,   // [3072, KAH] compact
            const float* __restrict__ gi,
            const float* __restrict__ b_hh,
            float* __restrict__ gh,                    // [4][B,3G]
            float* __restrict__ hall,                  // [T][B,G]
            __nv_bfloat16* __restrict__ hs) {          // [T*B, KAH] compact
    extern __shared__ char smem[];
    const uint32_t sb = smem_u32(smem);
    const int tid = threadIdx.x;
    const int wid = tid >> 5;
    const int lane = tid & 31;
    const int nb = blockIdx.x % 48;
    const int ky = blockIdx.x / 48;          // 0..3
    const int n0 = nb * 64;
    const int wm = wid >> 1, wn = wid & 1;
    unsigned seq = 0;

    for (int t = 0; t < T_; t++) {
        if (t > 0) {
            const __nv_bfloat16* A = hs + (long)(t - 1) * B_ * KAH;
            float acc[2][4][4];
            #pragma unroll
            for (int i = 0; i < 2; i++)
                #pragma unroll
                for (int j = 0; j < 4; j++)
                    #pragma unroll
                    for (int q = 0; q < 4; q++) acc[i][j][q] = 0.f;

            auto load_stage = [&](int lt, int s) {
                const int ts = ky * 12 + lt;             // global chunk 0..47
                const int ca = (ts < 32) ? ts : ts - 32;
                const int cb = (ts < 32) ? (ts & 15) : ts - 16;
                const uint32_t base = sb + (uint32_t)s * GSTAGE_B;
                const __nv_bfloat16* Ap = A + (long)ca * 64;
                const __nv_bfloat16* Bp = whhs + (long)n0 * KAH + (long)cb * 64;
                #pragma unroll
                for (int i = 0; i < 4; i++) {
                    int q = tid + i * 128;               // 0..511
                    int r = q >> 3, c = q & 7;
                    cp16(base + r * 128 + ((c ^ (r & 7)) << 4), Ap + (long)r * KAH + c * 8);
                }
                #pragma unroll
                for (int i = 0; i < 4; i++) {
                    int q = tid + i * 128;
                    int r = q >> 3, c = q & 7;
                    cp16(base + 8192 + r * 128 + ((c ^ (r & 7)) << 4), Bp + (long)r * KAH + c * 8);
                }
                cp_commit();
            };

            load_stage(0, 0);
            load_stage(1, 1);
            for (int lt = 0; lt < 12; lt++) {
                if (lt == 11) cp_wait<0>(); else cp_wait<1>();
                __syncthreads();
                if (lt + 2 < 12) load_stage(lt + 2, (lt + 2) % NSTAGE);

                const uint32_t ab = sb + (uint32_t)(lt % NSTAGE) * GSTAGE_B;
                const uint32_t bb = ab + 8192;
                #pragma unroll
                for (int ks = 0; ks < 4; ks++) {
                    uint32_t afr[2][4], bfr[2][4];
                    #pragma unroll
                    for (int mi = 0; mi < 2; mi++) {
                        int R = wm * 32 + mi * 16 + (lane & 7) + (((lane >> 3) & 1) << 3);
                        int cc = ks * 2 + (lane >> 4);
                        ldsm4(afr[mi], ab + R * 128 + (((cc ^ (R & 7)) & 7) << 4));
                    }
                    #pragma unroll
                    for (int bp = 0; bp < 2; bp++) {
                        int R = wn * 32 + bp * 16 + (lane & 7) + ((lane >> 4) << 3);
                        int cc = ks * 2 + ((lane >> 3) & 1);
                        ldsm4(bfr[bp], bb + R * 128 + (((cc ^ (R & 7)) & 7) << 4));
                    }
                    #pragma unroll
                    for (int mi = 0; mi < 2; mi++)
                        #pragma unroll
                        for (int nj = 0; nj < 4; nj++)
                            mma16816(acc[mi][nj], afr[mi], &bfr[nj >> 1][(nj & 1) * 2]);
                }
            }
            // write partial to gh[ky]
            float* Cy = gh + (long)ky * B_ * S3_;
            const int gq = lane >> 2;
            const int tg = lane & 3;
            #pragma unroll
            for (int mi = 0; mi < 2; mi++) {
                #pragma unroll
                for (int half = 0; half < 2; half++) {
                    int m = wm * 32 + mi * 16 + gq + half * 8;
                    #pragma unroll
                    for (int nj = 0; nj < 4; nj++) {
                        int n = n0 + wn * 32 + nj * 8 + tg * 2;
                        float2 v;
                        v.x = acc[mi][nj][half * 2 + 0];
                        v.y = acc[mi][nj][half * 2 + 1];
                        *(float2*)(Cy + (long)m * S3_ + n) = v;
                    }
                }
            }
        }
        gbar(++seq * GRU_CTAS);          // gh ready (or trivially at t=0)

        // gate phase: cover B*G = 65536 elems with 24576 threads
        const float* git = gi + (long)t * B_ * S3_;
        for (int i = blockIdx.x * 128 + tid; i < B_ * G_; i += GRU_CTAS * 128) {
            int b = i >> 10;
            int g = i & (G_ - 1);
            long o = (long)b * S3_;
            float ir = git[o + g];
            float iz = git[o + G_ + g];
            float in_ = git[o + 2 * G_ + g];
            float hr, hz, hn;
            if (t == 0) {
                hr = b_hh[g]; hz = b_hh[G_ + g]; hn = b_hh[2 * G_ + g];
            } else {
                const long P = (long)B_ * S3_;
                hr = __ldcg(gh + o + g) + __ldcg(gh + P + o + g)
                   + __ldcg(gh + 2 * P + o + g) + __ldcg(gh + 3 * P + o + g) + b_hh[g];
                hz = __ldcg(gh + o + G_ + g) + __ldcg(gh + P + o + G_ + g)
                   + __ldcg(gh + 2 * P + o + G_ + g) + __ldcg(gh + 3 * P + o + G_ + g)
                   + b_hh[G_ + g];
                hn = __ldcg(gh + o + 2 * G_ + g) + __ldcg(gh + P + o + 2 * G_ + g)
                   + __ldcg(gh + 2 * P + o + 2 * G_ + g) + __ldcg(gh + 3 * P + o + 2 * G_ + g)
                   + b_hh[2 * G_ + g];
            }
            float r = 1.f / (1.f + expf(-(ir + hr)));
            float z = 1.f / (1.f + expf(-(iz + hz)));
            float n = tanhf(in_ + r * hn);
            float hp = (t == 0) ? 0.f : hall[(long)(t - 1) * B_ * G_ + i];
            float hv = (1.f - z) * n + z * hp;
            hall[(long)t * B_ * G_ + i] = hv;
            __nv_bfloat16 hi = __float2bfloat16(hv);
            __nv_bfloat16* d = hs + ((long)t * B_ + b) * KAH + g;
            d[0] = hi;
            d[G_] = __float2bfloat16(hv - __bfloat162float(hi));
        }
        gbar(++seq * GRU_CTAS);          // hs(t) ready for gemm(t+1)
    }
}

// ================= launch ====================================================
extern "C" void kernel_launch(void* const* d_in, const int* in_sizes, int n_in,
                              void* d_out, int out_size) {
    (void)in_sizes; (void)n_in; (void)out_size;
    const float* features  = (const float*)d_in[0];
    const int*   input_ids = (const int*)  d_in[1];
    const float* emb_table = (const float*)d_in[2];
    const float* img_v     = (const float*)d_in[3];
    const float* img_g     = (const float*)d_in[4];
    const float* img_b     = (const float*)d_in[5];
    const float* W_ih      = (const float*)d_in[6];
    const float* W_hh      = (const float*)d_in[7];
    const float* b_ih      = (const float*)d_in[8];
    const float* b_hh      = (const float*)d_in[9];
    const float* fc_v      = (const float*)d_in[10];
    const float* fc_g      = (const float*)d_in[11];
    const float* fc_b      = (const float*)d_in[12];
    float* out = (float*)d_out;

    float *gi, *gh, *hall, *img_s;
    __nv_bfloat16 *xs, *wihs, *whhs, *hs, *fcs;
    unsigned* bar;
    cudaGetSymbolAddress((void**)&gi,    g_gi);
    cudaGetSymbolAddress((void**)&gh,    g_gh);
    cudaGetSymbolAddress((void**)&hall,  g_hall);
    cudaGetSymbolAddress((void**)&img_s, g_img_scale);
    cudaGetSymbolAddress((void**)&xs,    g_xs);
    cudaGetSymbolAddress((void**)&wihs,  g_wihs);
    cudaGetSymbolAddress((void**)&whhs,  g_whhs);
    cudaGetSymbolAddress((void**)&hs,    g_hs);
    cudaGetSymbolAddress((void**)&fcs,   g_fcs);
    cudaGetSymbolAddress((void**)&bar,   g_grubar);

    cudaFuncSetAttribute((const void*)gemm_mma<0, 8, KAX>,
                         cudaFuncAttributeMaxDynamicSharedMemorySize, MMA_SMEM);
    cudaFuncSetAttribute((const void*)gemm_mma<1, 16, KAH>,
                         cudaFuncAttributeMaxDynamicSharedMemorySize, MMA_SMEM);
    cudaFuncSetAttribute((const void*)gru_persist,
                         cudaFuncAttributeMaxDynamicSharedMemorySize, GRU_SMEM);

    // 1) img weight-norm scale
    rownorm_scale<<<E_, 256>>>(img_v, img_g, img_s, F_);
    // 2) imgs_embed -> compact split rows t=0 of xs
    gemm_img<32, 32, 32, 2, 2><<<dim3(E_ / 32, B_ / 32), 256>>>(
        features, img_v, img_s, img_b, xs, B_, E_, F_);
    // 3) gather embeddings (t>=1) -> xs  +  W_ih' -> wihs
    prep_combo<<<GATHER_BLKS + WIH_BLKS, 128>>>(input_ids, emb_table, W_ih, xs, wihs);
    // 4) gi_all = x' @ W_ih'^T + b_ih   (PROFILED LAUNCH #4)
    gemm_mma<0, 8, KAX><<<dim3(TB_ / 128, S3_ / 128), 512, MMA_SMEM>>>(
        xs, wihs, b_ih, gi, TB_, S3_);

    // W_hh' and fused fc prep (independent of GRU chain start)
    split2<<<(S3_ * G_) / 256, 256>>>(W_hh, whhs, G_, 10, KAH);
    prep_fc<<<V_, 128>>>(fc_v, fc_g, fcs);

    // GRU recurrence: one persistent kernel (barrier counter zeroed per replay)
    cudaMemsetAsync(bar, 0, sizeof(unsigned));
    gru_persist<<<GRU_CTAS, 128, GRU_SMEM>>>(whhs, gi, b_hh, gh, hall, hs);

    // fc on tensor cores, permuted epilogue
    gemm_mma<1, 16, KAH><<<dim3(TB_ / 128, V_ / 128), 512, MMA_SMEM>>>(
        hs, fcs, fc_b, out, TB_, V_);
}